// round 3
// baseline (speedup 1.0000x reference)
#include <cuda_runtime.h>
#include <math.h>

typedef unsigned long long ull;

#define EPS 1e-5f

// ---------------- scratch (device globals; no allocations allowed) ----------
__device__ float  g_om[8 * 27 * 64 * 64];          // offset-conv output
__device__ float  g_out1[8 * 256 * 64 * 64];       // DCN output (pre-BN)
__device__ float  g_raw[4 * 8 * 256 * 64 * 64];    // convT output per parity (pre-BN)
__device__ float  g_wdT2[9 * 256 * 512];           // DCN weights, lane-major dup pairs
__device__ float  g_woT[9 * 256 * 32];             // offset-conv weights [tap][c][o(pad32)]
__device__ float  g_wctT2[16 * 256 * 512];         // convT weights lane-major dup pairs
__device__ double g_red[1024];                     // sums/sumsqs for the two BNs
__device__ float  g_s1[256], g_t1[256], g_s2[256], g_t2[256];

// ---------------- packed f32x2 helpers --------------------------------------
__device__ __forceinline__ ull pk2(float a, float b) {
    ull r; asm("mov.b64 %0, {%1,%2};" : "=l"(r) : "f"(a), "f"(b)); return r;
}
__device__ __forceinline__ void upk2(ull v, float& a, float& b) {
    asm("mov.b64 {%0,%1}, %2;" : "=f"(a), "=f"(b) : "l"(v));
}
__device__ __forceinline__ void ffma2(ull& d, ull a, ull b) {
    asm("fma.rn.f32x2 %0, %1, %2, %0;" : "+l"(d) : "l"(a), "l"(b));
}

// ---------------- weight prep -----------------------------------------------
// Lane-major layout: ull index for (m, c, o) where m = tap (dcn) or par*4+tp (convT):
//   u = (((m*256 + c)*4 + ((o>>1)&3)) << 6) + ((o>>3)<<1) + (o&1)
// so the 16B chunk ((m,c,j), lane) holds the duplicated pairs for o = lane*8 + 2j, 2j+1.
__global__ void prep_wd(const float* __restrict__ w) {  // w_dcn [o][c][3][3]
    int idx = blockIdx.x * blockDim.x + threadIdx.x;
    if (idx >= 9 * 256 * 256) return;
    int tap = idx >> 16, c = (idx >> 8) & 255, o = idx & 255;
    float v = w[((o << 8) + c) * 9 + tap];
    size_t u = ((((size_t)tap * 256 + c) * 4 + ((o >> 1) & 3)) << 6) + ((o >> 3) << 1) + (o & 1);
    g_wdT2[u * 2] = v;
    g_wdT2[u * 2 + 1] = v;
}

__global__ void prep_wo(const float* __restrict__ w) {  // w_off [27][c][3][3]
    int idx = blockIdx.x * blockDim.x + threadIdx.x;
    if (idx >= 9 * 256 * 32) return;
    int tap = idx >> 13, c = (idx >> 5) & 255, o = idx & 31;
    g_woT[idx] = (o < 27) ? w[((o << 8) + c) * 9 + tap] : 0.f;
}

__global__ void prep_wct(const float* __restrict__ w) {  // w_ct [i][o][4][4]
    int idx = blockIdx.x * blockDim.x + threadIdx.x;
    if (idx >= 16 * 65536) return;
    int q = idx >> 16, c = (idx >> 8) & 255, o = idx & 255;
    int par = q >> 2, tp = q & 3;
    int py = par >> 1, px = par & 1, ty = tp >> 1, tx = tp & 1;
    int a = py ? (ty ? 0 : 2) : (ty ? 1 : 3);
    int b = px ? (tx ? 0 : 2) : (tx ? 1 : 3);
    float v = w[(((c << 8) + o) << 4) + (a << 2) + b];
    size_t u = ((((size_t)q * 256 + c) * 4 + ((o >> 1) & 3)) << 6) + ((o >> 3) << 1) + (o & 1);
    g_wctT2[u * 2] = v;
    g_wctT2[u * 2 + 1] = v;
}

__global__ void k_zero() {
    int t = threadIdx.x;
    g_red[t] = 0.0; g_red[256 + t] = 0.0; g_red[512 + t] = 0.0; g_red[768 + t] = 0.0;
}

// ---------------- offset conv: 256->27(pad 32), 3x3 SAME --------------------
__global__ void __launch_bounds__(256, 2) k_off(const float* __restrict__ x,
                                                const float* __restrict__ boff) {
    extern __shared__ float vsm[];             // [256 c][64 p]
    const int t = threadIdx.x, y = blockIdx.x, n = blockIdx.y;
    const int o  = t & 31;
    const int p0 = (t >> 5) * 8;
    const int p  = t & 63;
    const int cg = t >> 6;

    ull acc[4];
    float bo = (o < 27) ? boff[o] : 0.f;
    ull bb = pk2(bo, bo);
    acc[0] = bb; acc[1] = bb; acc[2] = bb; acc[3] = bb;

    const float* xn = x + ((size_t)n << 20);

    for (int tap = 0; tap < 9; tap++) {
        const int ki = tap / 3, kj = tap - 3 * ki;
        const int yy = y + ki - 1;
        const int xx = p + kj - 1;
        const bool valid = (yy >= 0) && (yy < 64) && (xx >= 0) && (xx < 64);
        const float* src = xn + yy * 64 + xx;
        #pragma unroll 4
        for (int i = 0; i < 64; i++) {
            const int c = cg + (i << 2);
            vsm[(c << 6) + p] = valid ? src[(size_t)c << 12] : 0.f;
        }
        __syncthreads();
        const float* wb = g_woT + ((tap << 8) << 5);
        #pragma unroll 2
        for (int c = 0; c < 256; c++) {
            float w = wb[(c << 5) + o];
            ull wd = pk2(w, w);
            const ulonglong2* vp = (const ulonglong2*)(vsm + (c << 6) + p0);
            ulonglong2 va = vp[0], vb = vp[1];
            ffma2(acc[0], wd, va.x);
            ffma2(acc[1], wd, va.y);
            ffma2(acc[2], wd, vb.x);
            ffma2(acc[3], wd, vb.y);
        }
        __syncthreads();
    }

    if (o < 27) {
        float f0,f1,f2,f3,f4,f5,f6,f7;
        upk2(acc[0], f0, f1); upk2(acc[1], f2, f3);
        upk2(acc[2], f4, f5); upk2(acc[3], f6, f7);
        float* op = g_om + (((size_t)(n * 27 + o) * 64 + y) << 6) + p0;
        *(float4*)op       = make_float4(f0, f1, f2, f3);
        *(float4*)(op + 4) = make_float4(f4, f5, f6, f7);
    }
}

// ---------------- DCNv2: gather + 9-tap GEMM, 2-row tiles -------------------
// Thread map: og = t>>3 (o-block of 8), pg = t&7 (16-pixel block of 128-px tile)
__global__ void __launch_bounds__(256, 1) k_dcn(const float* __restrict__ x,
                                                const float* __restrict__ bdcn) {
    extern __shared__ float vsm[];             // [256 c][128 p]
    const int t = threadIdx.x, by = blockIdx.x, n = blockIdx.y;
    const int y0 = by << 1;
    const int og = t >> 3;
    const int o0 = og << 3;
    const int pg = t & 7;
    const int p0 = pg << 4;
    const int rot = (pg >> 1) & 3;             // bank-conflict-killing read rotation
    const int fp = t & 127, fch = t >> 7;
    const int fy = y0 + (fp >> 6), fx = fp & 63;

    ull acc[64];
    #pragma unroll
    for (int io = 0; io < 8; io++) {
        float b = bdcn[o0 + io];
        ull bb = pk2(b, b);
        #pragma unroll
        for (int jp = 0; jp < 8; jp++) acc[io * 8 + jp] = bb;
    }

    const float* xn = x + ((size_t)n << 20);

    for (int tap = 0; tap < 9; tap++) {
        const int ki = tap / 3, kj = tap - 3 * ki;
        const float offy = g_om[(((n * 27 + 2 * tap)     * 64 + fy) << 6) + fx];
        const float offx = g_om[(((n * 27 + 2 * tap + 1) * 64 + fy) << 6) + fx];
        const float mm   = g_om[(((n * 27 + 18 + tap)    * 64 + fy) << 6) + fx];
        const float mask = 1.f / (1.f + __expf(-mm));
        const float ys = (float)(fy + ki - 1) + offy;
        const float xs = (float)(fx + kj - 1) + offx;
        const float fy0f = floorf(ys), fx0f = floorf(xs);
        const float dy = ys - fy0f, dx = xs - fx0f;
        const int iy0 = (int)fy0f, ix0 = (int)fx0f;
        const int iy1 = iy0 + 1, ix1 = ix0 + 1;
        const bool vy0 = (iy0 >= 0) && (iy0 < 64), vy1 = (iy1 >= 0) && (iy1 < 64);
        const bool vx0 = (ix0 >= 0) && (ix0 < 64), vx1 = (ix1 >= 0) && (ix1 < 64);
        const float w00 = (vy0 && vx0) ? (1.f - dy) * (1.f - dx) * mask : 0.f;
        const float w01 = (vy0 && vx1) ? (1.f - dy) * dx * mask : 0.f;
        const float w10 = (vy1 && vx0) ? dy * (1.f - dx) * mask : 0.f;
        const float w11 = (vy1 && vx1) ? dy * dx * mask : 0.f;
        const int cy0 = min(max(iy0, 0), 63), cy1 = min(max(iy1, 0), 63);
        const int cx0 = min(max(ix0, 0), 63), cx1 = min(max(ix1, 0), 63);
        const int a00 = cy0 * 64 + cx0, a01 = cy0 * 64 + cx1;
        const int a10 = cy1 * 64 + cx0, a11 = cy1 * 64 + cx1;

        #pragma unroll 4
        for (int i = 0; i < 128; i++) {
            const int c = (fch << 7) + i;
            const float* xc = xn + ((size_t)c << 12);
            vsm[(c << 7) + fp] = w00 * xc[a00] + w01 * xc[a01]
                               + w10 * xc[a10] + w11 * xc[a11];
        }
        __syncthreads();

        const ulonglong2* wt = (const ulonglong2*)g_wdT2 + ((size_t)tap << 15) + og;
        #pragma unroll 1
        for (int c = 0; c < 256; c++) {
            const ulonglong2* wp = wt + (c << 7);
            ulonglong2 w0 = wp[0], w1 = wp[32], w2 = wp[64], w3 = wp[96];
            const float* vbase = vsm + (c << 7) + p0;
            ulonglong2 vchunk[4];
            #pragma unroll
            for (int k = 0; k < 4; k++) {
                int j = (k + rot) & 3;
                vchunk[j] = *(const ulonglong2*)(vbase + (j << 2));
            }
            ull wv[8] = { w0.x, w0.y, w1.x, w1.y, w2.x, w2.y, w3.x, w3.y };
            ull vv[8] = { vchunk[0].x, vchunk[0].y, vchunk[1].x, vchunk[1].y,
                          vchunk[2].x, vchunk[2].y, vchunk[3].x, vchunk[3].y };
            #pragma unroll
            for (int io = 0; io < 8; io++)
                #pragma unroll
                for (int jp = 0; jp < 8; jp++)
                    ffma2(acc[io * 8 + jp], wv[io], vv[jp]);
        }
        __syncthreads();
    }

    const int row = y0 + (pg >> 2);
    const int col = (pg & 3) << 4;
    float* ob = g_out1 + ((size_t)n << 20) + (row << 6) + col;
    #pragma unroll
    for (int io = 0; io < 8; io++) {
        float f0,f1,f2,f3,f4,f5,f6,f7,f8,f9,fa,fb,fc,fd,fe,ff;
        upk2(acc[io * 8 + 0], f0, f1); upk2(acc[io * 8 + 1], f2, f3);
        upk2(acc[io * 8 + 2], f4, f5); upk2(acc[io * 8 + 3], f6, f7);
        upk2(acc[io * 8 + 4], f8, f9); upk2(acc[io * 8 + 5], fa, fb);
        upk2(acc[io * 8 + 6], fc, fd); upk2(acc[io * 8 + 7], fe, ff);
        float* op = ob + ((size_t)(o0 + io) << 12);
        *(float4*)(op +  0) = make_float4(f0, f1, f2, f3);
        *(float4*)(op +  4) = make_float4(f4, f5, f6, f7);
        *(float4*)(op +  8) = make_float4(f8, f9, fa, fb);
        *(float4*)(op + 12) = make_float4(fc, fd, fe, ff);
    }
}

// ---------------- per-channel reductions ------------------------------------
__global__ void k_red1() {
    int c = blockIdx.x, nb = blockIdx.y, t = threadIdx.x;
    const float4* p = (const float4*)(g_out1 + ((((size_t)nb << 8) + c) << 12));
    float s = 0.f, ss = 0.f;
    #pragma unroll
    for (int i = 0; i < 4; i++) {
        float4 v = p[t + (i << 8)];
        s  += v.x + v.y + v.z + v.w;
        ss += v.x * v.x + v.y * v.y + v.z * v.z + v.w * v.w;
    }
    for (int off = 16; off; off >>= 1) {
        s  += __shfl_down_sync(0xffffffffu, s, off);
        ss += __shfl_down_sync(0xffffffffu, ss, off);
    }
    __shared__ float as[8], bs[8];
    if ((t & 31) == 0) { as[t >> 5] = s; bs[t >> 5] = ss; }
    __syncthreads();
    if (t == 0) {
        float S = 0.f, SS = 0.f;
        for (int i = 0; i < 8; i++) { S += as[i]; SS += bs[i]; }
        atomicAdd(&g_red[c], (double)S);
        atomicAdd(&g_red[256 + c], (double)SS);
    }
}

__global__ void k_red2() {
    int c = blockIdx.x, q = blockIdx.y, t = threadIdx.x;
    const float4* p = (const float4*)(g_raw + ((((size_t)q << 8) + c) << 12));
    float s = 0.f, ss = 0.f;
    #pragma unroll
    for (int i = 0; i < 4; i++) {
        float4 v = p[t + (i << 8)];
        s  += v.x + v.y + v.z + v.w;
        ss += v.x * v.x + v.y * v.y + v.z * v.z + v.w * v.w;
    }
    for (int off = 16; off; off >>= 1) {
        s  += __shfl_down_sync(0xffffffffu, s, off);
        ss += __shfl_down_sync(0xffffffffu, ss, off);
    }
    __shared__ float as[8], bs[8];
    if ((t & 31) == 0) { as[t >> 5] = s; bs[t >> 5] = ss; }
    __syncthreads();
    if (t == 0) {
        float S = 0.f, SS = 0.f;
        for (int i = 0; i < 8; i++) { S += as[i]; SS += bs[i]; }
        atomicAdd(&g_red[512 + c], (double)S);
        atomicAdd(&g_red[768 + c], (double)SS);
    }
}

__global__ void k_stats1(const float* __restrict__ g, const float* __restrict__ b) {
    int t = threadIdx.x;
    double sum = g_red[t], sq = g_red[256 + t];
    double m = sum / 32768.0;
    float var = (float)(sq / 32768.0 - m * m);
    var = fmaxf(var, 0.f);
    float s = g[t] * rsqrtf(var + EPS);
    g_s1[t] = s;
    g_t1[t] = b[t] - (float)m * s;
}

__global__ void k_stats2(const float* __restrict__ g, const float* __restrict__ b) {
    int t = threadIdx.x;
    double sum = g_red[512 + t], sq = g_red[768 + t];
    double m = sum / 131072.0;
    float var = (float)(sq / 131072.0 - m * m);
    var = fmaxf(var, 0.f);
    float s = g[t] * rsqrtf(var + EPS);
    g_s2[t] = s;
    g_t2[t] = b[t] - (float)m * s;
}

// ---------------- conv transpose (per output parity, 4 taps), 2-row tiles ---
__global__ void __launch_bounds__(256, 1) k_convt() {
    extern __shared__ float sm[];
    float* vsm = sm;                 // [256][128]
    float* ssm = sm + 32768;         // s1
    float* tsm = sm + 33024;         // t1
    const int t = threadIdx.x, by = blockIdx.x, n = blockIdx.y, par = blockIdx.z;
    const int py = par >> 1, px = par & 1;
    ssm[t] = g_s1[t];
    tsm[t] = g_t1[t];
    __syncthreads();

    const int ty0 = by << 1;
    const int og = t >> 3;
    const int o0 = og << 3;
    const int pg = t & 7;
    const int p0 = pg << 4;
    const int rot = (pg >> 1) & 3;
    const int fp = t & 127, fch = t >> 7;
    const int fty = ty0 + (fp >> 6), fx = fp & 63;

    ull acc[64];
    #pragma unroll
    for (int i = 0; i < 64; i++) acc[i] = 0ull;

    const float* srcn = g_out1 + ((size_t)n << 20);

    for (int tp = 0; tp < 4; tp++) {
        const int t_y = tp >> 1, t_x = tp & 1;
        const int yy = fty + t_y - 1 + py;
        const int xx = fx + t_x - 1 + px;
        const bool valid = (yy >= 0) && (yy < 64) && (xx >= 0) && (xx < 64);
        const float* src = srcn + yy * 64 + xx;
        #pragma unroll 4
        for (int i = 0; i < 128; i++) {
            const int c = (fch << 7) + i;
            float v = 0.f;
            if (valid) {
                float r = src[(size_t)c << 12];
                v = fmaxf(ssm[c] * r + tsm[c], 0.f);
            }
            vsm[(c << 7) + fp] = v;
        }
        __syncthreads();

        const int q = par * 4 + tp;
        const ulonglong2* wt = (const ulonglong2*)g_wctT2 + ((size_t)q << 15) + og;
        #pragma unroll 1
        for (int c = 0; c < 256; c++) {
            const ulonglong2* wp = wt + (c << 7);
            ulonglong2 w0 = wp[0], w1 = wp[32], w2 = wp[64], w3 = wp[96];
            const float* vbase = vsm + (c << 7) + p0;
            ulonglong2 vchunk[4];
            #pragma unroll
            for (int k = 0; k < 4; k++) {
                int j = (k + rot) & 3;
                vchunk[j] = *(const ulonglong2*)(vbase + (j << 2));
            }
            ull wv[8] = { w0.x, w0.y, w1.x, w1.y, w2.x, w2.y, w3.x, w3.y };
            ull vv[8] = { vchunk[0].x, vchunk[0].y, vchunk[1].x, vchunk[1].y,
                          vchunk[2].x, vchunk[2].y, vchunk[3].x, vchunk[3].y };
            #pragma unroll
            for (int io = 0; io < 8; io++)
                #pragma unroll
                for (int jp = 0; jp < 8; jp++)
                    ffma2(acc[io * 8 + jp], wv[io], vv[jp]);
        }
        __syncthreads();
    }

    const int row = ty0 + (pg >> 2);
    const int col = (pg & 3) << 4;
    float* ob = g_raw + (((size_t)par * 8 + n) << 20) + (row << 6) + col;
    #pragma unroll
    for (int io = 0; io < 8; io++) {
        float f0,f1,f2,f3,f4,f5,f6,f7,f8,f9,fa,fb,fc,fd,fe,ff;
        upk2(acc[io * 8 + 0], f0, f1); upk2(acc[io * 8 + 1], f2, f3);
        upk2(acc[io * 8 + 2], f4, f5); upk2(acc[io * 8 + 3], f6, f7);
        upk2(acc[io * 8 + 4], f8, f9); upk2(acc[io * 8 + 5], fa, fb);
        upk2(acc[io * 8 + 6], fc, fd); upk2(acc[io * 8 + 7], fe, ff);
        float* op = ob + ((size_t)(o0 + io) << 12);
        *(float4*)(op +  0) = make_float4(f0, f1, f2, f3);
        *(float4*)(op +  4) = make_float4(f4, f5, f6, f7);
        *(float4*)(op +  8) = make_float4(f8, f9, fa, fb);
        *(float4*)(op + 12) = make_float4(fc, fd, fe, ff);
    }
}

// ---------------- finalize: BN2 + ReLU, de-interleave parities --------------
__global__ void k_final(float* __restrict__ out) {
    int idx = blockIdx.x * 256 + threadIdx.x;
    int tx = idx & 63;
    int oy = (idx >> 6) & 127;
    int o  = (idx >> 13) & 255;
    int n  = idx >> 21;
    int py = oy & 1, ty = oy >> 1;
    size_t b0 = ((((size_t)(2 * py + 0) * 8 + n) * 256 + o) << 12) + (ty << 6) + tx;
    size_t b1 = ((((size_t)(2 * py + 1) * 8 + n) * 256 + o) << 12) + (ty << 6) + tx;
    float r0 = g_raw[b0], r1 = g_raw[b1];
    float s = g_s2[o], tt = g_t2[o];
    float2 w2;
    w2.x = fmaxf(s * r0 + tt, 0.f);
    w2.y = fmaxf(s * r1 + tt, 0.f);
    *(float2*)(out + ((((size_t)n * 256 + o) * 128 + oy) << 7) + 2 * tx) = w2;
}

// ---------------- launch ----------------------------------------------------
extern "C" void kernel_launch(void* const* d_in, const int* in_sizes, int n_in,
                              void* d_out, int out_size) {
    const float* x      = (const float*)d_in[0];
    const float* w_off  = (const float*)d_in[1];
    const float* b_off  = (const float*)d_in[2];
    const float* w_dcn  = (const float*)d_in[3];
    const float* b_dcn  = (const float*)d_in[4];
    const float* gamma1 = (const float*)d_in[5];
    const float* beta1  = (const float*)d_in[6];
    const float* w_ct   = (const float*)d_in[7];
    const float* gamma2 = (const float*)d_in[8];
    const float* beta2  = (const float*)d_in[9];
    float* out = (float*)d_out;

    cudaFuncSetAttribute(k_off,   cudaFuncAttributeMaxDynamicSharedMemorySize, 65536);
    cudaFuncSetAttribute(k_dcn,   cudaFuncAttributeMaxDynamicSharedMemorySize, 131072);
    cudaFuncSetAttribute(k_convt, cudaFuncAttributeMaxDynamicSharedMemorySize, 133120);

    prep_wd<<<(9 * 256 * 256 + 255) / 256, 256>>>(w_dcn);
    prep_wo<<<(9 * 256 * 32 + 255) / 256, 256>>>(w_off);
    prep_wct<<<(16 * 65536 + 255) / 256, 256>>>(w_ct);
    k_zero<<<1, 256>>>();

    k_off<<<dim3(64, 8), 256, 65536>>>(x, b_off);
    k_dcn<<<dim3(32, 8), 256, 131072>>>(x, b_dcn);

    k_red1<<<dim3(256, 8), 256>>>();
    k_stats1<<<1, 256>>>(gamma1, beta1);

    k_convt<<<dim3(32, 8, 4), 256, 133120>>>();

    k_red2<<<dim3(256, 32), 256>>>();
    k_stats2<<<1, 256>>>(gamma2, beta2);

    k_final<<<65536, 256>>>(out);
}

// round 4
// speedup vs baseline: 2.5643x; 2.5643x over previous
#include <cuda_runtime.h>
#include <math.h>

typedef unsigned long long ull;

#define EPS 1e-5f

// ---------------- scratch (device globals; no allocations allowed) ----------
__device__ float  g_om[8 * 27 * 64 * 64];          // offset-conv output
__device__ float  g_out1[8 * 256 * 64 * 64];       // DCN output (pre-BN)
__device__ float  g_raw[4 * 8 * 256 * 64 * 64];    // convT output per parity (pre-BN)
__device__ float  g_wdT2[9 * 256 * 512];           // DCN weights, lane-major dup pairs
__device__ float  g_woT[9 * 256 * 32];             // offset-conv weights [tap][c][o(pad32)]
__device__ float  g_wctT2[16 * 256 * 512];         // convT weights lane-major dup pairs
__device__ double g_red[1024];                     // sums/sumsqs for the two BNs
__device__ float  g_s1[256], g_t1[256], g_s2[256], g_t2[256];

// ---------------- packed f32x2 helpers --------------------------------------
__device__ __forceinline__ ull pk2(float a, float b) {
    ull r; asm("mov.b64 %0, {%1,%2};" : "=l"(r) : "f"(a), "f"(b)); return r;
}
__device__ __forceinline__ void upk2(ull v, float& a, float& b) {
    asm("mov.b64 {%0,%1}, %2;" : "=f"(a), "=f"(b) : "l"(v));
}
__device__ __forceinline__ void ffma2(ull& d, ull a, ull b) {
    asm("fma.rn.f32x2 %0, %1, %2, %0;" : "+l"(d) : "l"(a), "l"(b));
}

// ---------------- weight prep -----------------------------------------------
// Lane-major dup layout, ull index for (m, c, o):
//   u = (((m*256 + c)*4 + ((o>>1)&3)) << 6) + ((o>>3)<<1) + (o&1)
// Thread with og = o>>3 reads ulonglong2 (j*32 + og) for j = 0..3 to get its 8
// duplicated o-pairs; 8 lanes per og broadcast the same address.
__global__ void prep_wd(const float* __restrict__ w) {  // w_dcn [o][c][3][3]
    int idx = blockIdx.x * blockDim.x + threadIdx.x;
    if (idx >= 9 * 256 * 256) return;
    int tap = idx >> 16, c = (idx >> 8) & 255, o = idx & 255;
    float v = w[((o << 8) + c) * 9 + tap];
    size_t u = ((((size_t)tap * 256 + c) * 4 + ((o >> 1) & 3)) << 6) + ((o >> 3) << 1) + (o & 1);
    g_wdT2[u * 2] = v;
    g_wdT2[u * 2 + 1] = v;
}

__global__ void prep_wo(const float* __restrict__ w) {  // w_off [27][c][3][3]
    int idx = blockIdx.x * blockDim.x + threadIdx.x;
    if (idx >= 9 * 256 * 32) return;
    int tap = idx >> 13, c = (idx >> 5) & 255, o = idx & 31;
    g_woT[idx] = (o < 27) ? w[((o << 8) + c) * 9 + tap] : 0.f;
}

__global__ void prep_wct(const float* __restrict__ w) {  // w_ct [i][o][4][4]
    int idx = blockIdx.x * blockDim.x + threadIdx.x;
    if (idx >= 16 * 65536) return;
    int q = idx >> 16, c = (idx >> 8) & 255, o = idx & 255;
    int par = q >> 2, tp = q & 3;
    int py = par >> 1, px = par & 1, ty = tp >> 1, tx = tp & 1;
    int a = py ? (ty ? 0 : 2) : (ty ? 1 : 3);
    int b = px ? (tx ? 0 : 2) : (tx ? 1 : 3);
    float v = w[(((c << 8) + o) << 4) + (a << 2) + b];
    size_t u = ((((size_t)q * 256 + c) * 4 + ((o >> 1) & 3)) << 6) + ((o >> 3) << 1) + (o & 1);
    g_wctT2[u * 2] = v;
    g_wctT2[u * 2 + 1] = v;
}

__global__ void k_zero() {
    int t = threadIdx.x;
    g_red[t] = 0.0; g_red[256 + t] = 0.0; g_red[512 + t] = 0.0; g_red[768 + t] = 0.0;
}

// ---------------- offset conv: 256->27(pad 32), 3x3 SAME --------------------
__global__ void __launch_bounds__(256, 2) k_off(const float* __restrict__ x,
                                                const float* __restrict__ boff) {
    extern __shared__ float vsm[];             // [256 c][64 p]
    const int t = threadIdx.x, y = blockIdx.x, n = blockIdx.y;
    const int o  = t & 31;
    const int p0 = (t >> 5) * 8;
    const int p  = t & 63;
    const int cg = t >> 6;

    ull acc[4];
    float bo = (o < 27) ? boff[o] : 0.f;
    ull bb = pk2(bo, bo);
    acc[0] = bb; acc[1] = bb; acc[2] = bb; acc[3] = bb;

    const float* xn = x + ((size_t)n << 20);

    for (int tap = 0; tap < 9; tap++) {
        const int ki = tap / 3, kj = tap - 3 * ki;
        const int yy = y + ki - 1;
        const int xx = p + kj - 1;
        const bool valid = (yy >= 0) && (yy < 64) && (xx >= 0) && (xx < 64);
        const float* src = xn + yy * 64 + xx;
        #pragma unroll 4
        for (int i = 0; i < 64; i++) {
            const int c = cg + (i << 2);
            vsm[(c << 6) + p] = valid ? src[(size_t)c << 12] : 0.f;
        }
        __syncthreads();
        const float* wb = g_woT + ((tap << 8) << 5);
        #pragma unroll 2
        for (int c = 0; c < 256; c++) {
            float w = wb[(c << 5) + o];
            ull wd = pk2(w, w);
            const ulonglong2* vp = (const ulonglong2*)(vsm + (c << 6) + p0);
            ulonglong2 va = vp[0], vb = vp[1];
            ffma2(acc[0], wd, va.x);
            ffma2(acc[1], wd, va.y);
            ffma2(acc[2], wd, vb.x);
            ffma2(acc[3], wd, vb.y);
        }
        __syncthreads();
    }

    if (o < 27) {
        float f0,f1,f2,f3,f4,f5,f6,f7;
        upk2(acc[0], f0, f1); upk2(acc[1], f2, f3);
        upk2(acc[2], f4, f5); upk2(acc[3], f6, f7);
        float* op = g_om + (((size_t)(n * 27 + o) * 64 + y) << 6) + p0;
        *(float4*)op       = make_float4(f0, f1, f2, f3);
        *(float4*)(op + 4) = make_float4(f4, f5, f6, f7);
    }
}

// ---------------- DCNv2: gather + 9-tap GEMM, 1-row tiles -------------------
// Thread map: og = t>>3 (o-block of 8), pg = t&7 (8-pixel block of 64-px row).
// 8 lanes per og -> weight LDGs are warp-broadcast (256 B/warp/c).
__global__ void __launch_bounds__(256, 2) k_dcn(const float* __restrict__ x,
                                                const float* __restrict__ bdcn) {
    extern __shared__ float vsm[];             // [256 c][64 p]
    const int t = threadIdx.x, y = blockIdx.x, n = blockIdx.y;
    const int og = t >> 3;
    const int o0 = og << 3;
    const int pg = t & 7;
    const int p0 = pg << 3;
    const int p  = t & 63;
    const int cg = t >> 6;

    ull acc[32];
    #pragma unroll
    for (int io = 0; io < 8; io++) {
        float b = bdcn[o0 + io];
        ull bb = pk2(b, b);
        #pragma unroll
        for (int jp = 0; jp < 4; jp++) acc[io * 4 + jp] = bb;
    }

    const float* xn = x + ((size_t)n << 20);

    for (int tap = 0; tap < 9; tap++) {
        const int ki = tap / 3, kj = tap - 3 * ki;
        const float offy = g_om[(((n * 27 + 2 * tap)     * 64 + y) << 6) + p];
        const float offx = g_om[(((n * 27 + 2 * tap + 1) * 64 + y) << 6) + p];
        const float mm   = g_om[(((n * 27 + 18 + tap)    * 64 + y) << 6) + p];
        const float mask = 1.f / (1.f + __expf(-mm));
        const float ys = (float)(y + ki - 1) + offy;
        const float xs = (float)(p + kj - 1) + offx;
        const float fy0 = floorf(ys), fx0 = floorf(xs);
        const float dy = ys - fy0, dx = xs - fx0;
        const int iy0 = (int)fy0, ix0 = (int)fx0;
        const int iy1 = iy0 + 1, ix1 = ix0 + 1;
        const bool vy0 = (iy0 >= 0) && (iy0 < 64), vy1 = (iy1 >= 0) && (iy1 < 64);
        const bool vx0 = (ix0 >= 0) && (ix0 < 64), vx1 = (ix1 >= 0) && (ix1 < 64);
        const float w00 = (vy0 && vx0) ? (1.f - dy) * (1.f - dx) * mask : 0.f;
        const float w01 = (vy0 && vx1) ? (1.f - dy) * dx * mask : 0.f;
        const float w10 = (vy1 && vx0) ? dy * (1.f - dx) * mask : 0.f;
        const float w11 = (vy1 && vx1) ? dy * dx * mask : 0.f;
        const int cy0 = min(max(iy0, 0), 63), cy1 = min(max(iy1, 0), 63);
        const int cx0 = min(max(ix0, 0), 63), cx1 = min(max(ix1, 0), 63);
        const int a00 = cy0 * 64 + cx0, a01 = cy0 * 64 + cx1;
        const int a10 = cy1 * 64 + cx0, a11 = cy1 * 64 + cx1;

        #pragma unroll 4
        for (int i = 0; i < 64; i++) {
            const int c = cg + (i << 2);
            const float* xc = xn + ((size_t)c << 12);
            vsm[(c << 6) + p] = w00 * xc[a00] + w01 * xc[a01]
                              + w10 * xc[a10] + w11 * xc[a11];
        }
        __syncthreads();

        const ulonglong2* wt = (const ulonglong2*)g_wdT2 + ((size_t)tap << 15) + og;
        #pragma unroll 1
        for (int c = 0; c < 256; c++) {
            const ulonglong2* wp = wt + (c << 7);
            ulonglong2 w0 = wp[0], w1 = wp[32], w2 = wp[64], w3 = wp[96];
            const ulonglong2* vp = (const ulonglong2*)(vsm + (c << 6) + p0);
            ulonglong2 va = vp[0], vb = vp[1];
            ull wv[8] = { w0.x, w0.y, w1.x, w1.y, w2.x, w2.y, w3.x, w3.y };
            ull vv[4] = { va.x, va.y, vb.x, vb.y };
            #pragma unroll
            for (int io = 0; io < 8; io++)
                #pragma unroll
                for (int jp = 0; jp < 4; jp++)
                    ffma2(acc[io * 4 + jp], wv[io], vv[jp]);
        }
        __syncthreads();
    }

    float* ob = g_out1 + ((size_t)n << 20) + (y << 6) + p0;
    #pragma unroll
    for (int io = 0; io < 8; io++) {
        float f0,f1,f2,f3,f4,f5,f6,f7;
        upk2(acc[io * 4 + 0], f0, f1); upk2(acc[io * 4 + 1], f2, f3);
        upk2(acc[io * 4 + 2], f4, f5); upk2(acc[io * 4 + 3], f6, f7);
        float* op = ob + ((size_t)(o0 + io) << 12);
        *(float4*)op       = make_float4(f0, f1, f2, f3);
        *(float4*)(op + 4) = make_float4(f4, f5, f6, f7);
    }
}

// ---------------- per-channel reductions ------------------------------------
__global__ void k_red1() {
    int c = blockIdx.x, nb = blockIdx.y, t = threadIdx.x;
    const float4* p = (const float4*)(g_out1 + ((((size_t)nb << 8) + c) << 12));
    float s = 0.f, ss = 0.f;
    #pragma unroll
    for (int i = 0; i < 4; i++) {
        float4 v = p[t + (i << 8)];
        s  += v.x + v.y + v.z + v.w;
        ss += v.x * v.x + v.y * v.y + v.z * v.z + v.w * v.w;
    }
    for (int off = 16; off; off >>= 1) {
        s  += __shfl_down_sync(0xffffffffu, s, off);
        ss += __shfl_down_sync(0xffffffffu, ss, off);
    }
    __shared__ float as[8], bs[8];
    if ((t & 31) == 0) { as[t >> 5] = s; bs[t >> 5] = ss; }
    __syncthreads();
    if (t == 0) {
        float S = 0.f, SS = 0.f;
        for (int i = 0; i < 8; i++) { S += as[i]; SS += bs[i]; }
        atomicAdd(&g_red[c], (double)S);
        atomicAdd(&g_red[256 + c], (double)SS);
    }
}

__global__ void k_red2() {
    int c = blockIdx.x, q = blockIdx.y, t = threadIdx.x;
    const float4* p = (const float4*)(g_raw + ((((size_t)q << 8) + c) << 12));
    float s = 0.f, ss = 0.f;
    #pragma unroll
    for (int i = 0; i < 4; i++) {
        float4 v = p[t + (i << 8)];
        s  += v.x + v.y + v.z + v.w;
        ss += v.x * v.x + v.y * v.y + v.z * v.z + v.w * v.w;
    }
    for (int off = 16; off; off >>= 1) {
        s  += __shfl_down_sync(0xffffffffu, s, off);
        ss += __shfl_down_sync(0xffffffffu, ss, off);
    }
    __shared__ float as[8], bs[8];
    if ((t & 31) == 0) { as[t >> 5] = s; bs[t >> 5] = ss; }
    __syncthreads();
    if (t == 0) {
        float S = 0.f, SS = 0.f;
        for (int i = 0; i < 8; i++) { S += as[i]; SS += bs[i]; }
        atomicAdd(&g_red[512 + c], (double)S);
        atomicAdd(&g_red[768 + c], (double)SS);
    }
}

__global__ void k_stats1(const float* __restrict__ g, const float* __restrict__ b) {
    int t = threadIdx.x;
    double sum = g_red[t], sq = g_red[256 + t];
    double m = sum / 32768.0;
    float var = (float)(sq / 32768.0 - m * m);
    var = fmaxf(var, 0.f);
    float s = g[t] * rsqrtf(var + EPS);
    g_s1[t] = s;
    g_t1[t] = b[t] - (float)m * s;
}

__global__ void k_stats2(const float* __restrict__ g, const float* __restrict__ b) {
    int t = threadIdx.x;
    double sum = g_red[512 + t], sq = g_red[768 + t];
    double m = sum / 131072.0;
    float var = (float)(sq / 131072.0 - m * m);
    var = fmaxf(var, 0.f);
    float s = g[t] * rsqrtf(var + EPS);
    g_s2[t] = s;
    g_t2[t] = b[t] - (float)m * s;
}

// ---------------- conv transpose (per output parity, 4 taps), 1-row tiles ---
__global__ void __launch_bounds__(256, 2) k_convt() {
    extern __shared__ float sm[];
    float* vsm = sm;                 // [256][64]
    float* ssm = sm + 16384;         // s1
    float* tsm = sm + 16640;         // t1
    const int t = threadIdx.x, ty0 = blockIdx.x, n = blockIdx.y, par = blockIdx.z;
    const int py = par >> 1, px = par & 1;
    ssm[t] = g_s1[t];
    tsm[t] = g_t1[t];
    __syncthreads();

    const int og = t >> 3;
    const int o0 = og << 3;
    const int pg = t & 7;
    const int p0 = pg << 3;
    const int p  = t & 63;
    const int cg = t >> 6;

    ull acc[32];
    #pragma unroll
    for (int i = 0; i < 32; i++) acc[i] = 0ull;

    const float* srcn = g_out1 + ((size_t)n << 20);

    for (int tp = 0; tp < 4; tp++) {
        const int t_y = tp >> 1, t_x = tp & 1;
        const int yy = ty0 + t_y - 1 + py;
        const int xx = p + t_x - 1 + px;
        const bool valid = (yy >= 0) && (yy < 64) && (xx >= 0) && (xx < 64);
        const float* src = srcn + yy * 64 + xx;
        #pragma unroll 4
        for (int i = 0; i < 64; i++) {
            const int c = cg + (i << 2);
            float v = 0.f;
            if (valid) {
                float r = src[(size_t)c << 12];
                v = fmaxf(ssm[c] * r + tsm[c], 0.f);
            }
            vsm[(c << 6) + p] = v;
        }
        __syncthreads();

        const int q = par * 4 + tp;
        const ulonglong2* wt = (const ulonglong2*)g_wctT2 + ((size_t)q << 15) + og;
        #pragma unroll 1
        for (int c = 0; c < 256; c++) {
            const ulonglong2* wp = wt + (c << 7);
            ulonglong2 w0 = wp[0], w1 = wp[32], w2 = wp[64], w3 = wp[96];
            const ulonglong2* vp = (const ulonglong2*)(vsm + (c << 6) + p0);
            ulonglong2 va = vp[0], vb = vp[1];
            ull wv[8] = { w0.x, w0.y, w1.x, w1.y, w2.x, w2.y, w3.x, w3.y };
            ull vv[4] = { va.x, va.y, vb.x, vb.y };
            #pragma unroll
            for (int io = 0; io < 8; io++)
                #pragma unroll
                for (int jp = 0; jp < 4; jp++)
                    ffma2(acc[io * 4 + jp], wv[io], vv[jp]);
        }
        __syncthreads();
    }

    float* ob = g_raw + (((size_t)par * 8 + n) << 20) + (ty0 << 6) + p0;
    #pragma unroll
    for (int io = 0; io < 8; io++) {
        float f0,f1,f2,f3,f4,f5,f6,f7;
        upk2(acc[io * 4 + 0], f0, f1); upk2(acc[io * 4 + 1], f2, f3);
        upk2(acc[io * 4 + 2], f4, f5); upk2(acc[io * 4 + 3], f6, f7);
        float* op = ob + ((size_t)(o0 + io) << 12);
        *(float4*)op       = make_float4(f0, f1, f2, f3);
        *(float4*)(op + 4) = make_float4(f4, f5, f6, f7);
    }
}

// ---------------- finalize: BN2 + ReLU, de-interleave parities --------------
__global__ void k_final(float* __restrict__ out) {
    int idx = blockIdx.x * 256 + threadIdx.x;
    int tx = idx & 63;
    int oy = (idx >> 6) & 127;
    int o  = (idx >> 13) & 255;
    int n  = idx >> 21;
    int py = oy & 1, ty = oy >> 1;
    size_t b0 = ((((size_t)(2 * py + 0) * 8 + n) * 256 + o) << 12) + (ty << 6) + tx;
    size_t b1 = ((((size_t)(2 * py + 1) * 8 + n) * 256 + o) << 12) + (ty << 6) + tx;
    float r0 = g_raw[b0], r1 = g_raw[b1];
    float s = g_s2[o], tt = g_t2[o];
    float2 w2;
    w2.x = fmaxf(s * r0 + tt, 0.f);
    w2.y = fmaxf(s * r1 + tt, 0.f);
    *(float2*)(out + ((((size_t)n * 256 + o) * 128 + oy) << 7) + 2 * tx) = w2;
}

// ---------------- launch ----------------------------------------------------
extern "C" void kernel_launch(void* const* d_in, const int* in_sizes, int n_in,
                              void* d_out, int out_size) {
    const float* x      = (const float*)d_in[0];
    const float* w_off  = (const float*)d_in[1];
    const float* b_off  = (const float*)d_in[2];
    const float* w_dcn  = (const float*)d_in[3];
    const float* b_dcn  = (const float*)d_in[4];
    const float* gamma1 = (const float*)d_in[5];
    const float* beta1  = (const float*)d_in[6];
    const float* w_ct   = (const float*)d_in[7];
    const float* gamma2 = (const float*)d_in[8];
    const float* beta2  = (const float*)d_in[9];
    float* out = (float*)d_out;

    cudaFuncSetAttribute(k_off,   cudaFuncAttributeMaxDynamicSharedMemorySize, 65536);
    cudaFuncSetAttribute(k_dcn,   cudaFuncAttributeMaxDynamicSharedMemorySize, 65536);
    cudaFuncSetAttribute(k_convt, cudaFuncAttributeMaxDynamicSharedMemorySize, 67584);

    prep_wd<<<(9 * 256 * 256 + 255) / 256, 256>>>(w_dcn);
    prep_wo<<<(9 * 256 * 32 + 255) / 256, 256>>>(w_off);
    prep_wct<<<(16 * 65536 + 255) / 256, 256>>>(w_ct);
    k_zero<<<1, 256>>>();

    k_off<<<dim3(64, 8), 256, 65536>>>(x, b_off);
    k_dcn<<<dim3(64, 8), 256, 65536>>>(x, b_dcn);

    k_red1<<<dim3(256, 8), 256>>>();
    k_stats1<<<1, 256>>>(gamma1, beta1);

    k_convt<<<dim3(64, 8, 4), 256, 67584>>>();

    k_red2<<<dim3(256, 32), 256>>>();
    k_stats2<<<1, 256>>>(gamma2, beta2);

    k_final<<<65536, 256>>>(out);
}

// round 5
// speedup vs baseline: 2.7812x; 1.0846x over previous
#include <cuda_runtime.h>
#include <math.h>

typedef unsigned long long ull;

#define EPS 1e-5f

// ---------------- scratch (device globals; no allocations allowed) ----------
__device__ float  g_om[8 * 27 * 64 * 64];          // offset-conv output
__device__ float  g_out1[8 * 256 * 64 * 64];       // DCN output (pre-BN)
__device__ float  g_raw[4 * 8 * 256 * 64 * 64];    // convT output per parity (pre-BN)
__device__ float  g_wdT[9 * 256 * 256];            // DCN weights [tap][c][o]
__device__ float  g_woT[9 * 256 * 32];             // offset-conv weights [tap][c][o(pad32)]
__device__ float  g_wctT[16 * 256 * 256];          // convT weights [par*4+tp][c][o]
__device__ double g_red[1024];                     // sums/sumsqs for the two BNs
__device__ float  g_s1[256], g_t1[256], g_s2[256], g_t2[256];

// ---------------- packed f32x2 helpers --------------------------------------
__device__ __forceinline__ ull pk2(float a, float b) {
    ull r; asm("mov.b64 %0, {%1,%2};" : "=l"(r) : "f"(a), "f"(b)); return r;
}
__device__ __forceinline__ void upk2(ull v, float& a, float& b) {
    asm("mov.b64 {%0,%1}, %2;" : "=f"(a), "=f"(b) : "l"(v));
}
__device__ __forceinline__ void ffma2(ull& d, ull a, ull b) {
    asm("fma.rn.f32x2 %0, %1, %2, %0;" : "+l"(d) : "l"(a), "l"(b));
}

// ---------------- weight prep -----------------------------------------------
__global__ void prep_wd(const float* __restrict__ w) {  // w_dcn [o][c][3][3]
    int idx = blockIdx.x * blockDim.x + threadIdx.x;
    if (idx >= 9 * 256 * 256) return;
    int tap = idx >> 16, c = (idx >> 8) & 255, o = idx & 255;
    g_wdT[idx] = w[((o << 8) + c) * 9 + tap];
}

__global__ void prep_wo(const float* __restrict__ w) {  // w_off [27][c][3][3]
    int idx = blockIdx.x * blockDim.x + threadIdx.x;
    if (idx >= 9 * 256 * 32) return;
    int tap = idx >> 13, c = (idx >> 5) & 255, o = idx & 31;
    g_woT[idx] = (o < 27) ? w[((o << 8) + c) * 9 + tap] : 0.f;
}

__global__ void prep_wct(const float* __restrict__ w) {  // w_ct [i][o][4][4]
    int idx = blockIdx.x * blockDim.x + threadIdx.x;
    if (idx >= 16 * 65536) return;
    int q = idx >> 16, c = (idx >> 8) & 255, o = idx & 255;
    int par = q >> 2, tp = q & 3;
    int py = par >> 1, px = par & 1, ty = tp >> 1, tx = tp & 1;
    int a = py ? (ty ? 0 : 2) : (ty ? 1 : 3);
    int b = px ? (tx ? 0 : 2) : (tx ? 1 : 3);
    g_wctT[idx] = w[(((c << 8) + o) << 4) + (a << 2) + b];
}

__global__ void k_zero() {
    int t = threadIdx.x;
    g_red[t] = 0.0; g_red[256 + t] = 0.0; g_red[512 + t] = 0.0; g_red[768 + t] = 0.0;
}

// ---------------- offset conv: 256->27(pad 32), 3x3 SAME --------------------
__global__ void __launch_bounds__(256, 2) k_off(const float* __restrict__ x,
                                                const float* __restrict__ boff) {
    extern __shared__ float vsm[];             // [256 c][64 p]
    const int t = threadIdx.x, y = blockIdx.x, n = blockIdx.y;
    const int o  = t & 31;
    const int p0 = (t >> 5) * 8;
    const int p  = t & 63;
    const int cg = t >> 6;

    ull acc[4];
    float bo = (o < 27) ? boff[o] : 0.f;
    ull bb = pk2(bo, bo);
    acc[0] = bb; acc[1] = bb; acc[2] = bb; acc[3] = bb;

    const float* xn = x + ((size_t)n << 20);

    for (int tap = 0; tap < 9; tap++) {
        const int ki = tap / 3, kj = tap - 3 * ki;
        const int yy = y + ki - 1;
        const int xx = p + kj - 1;
        const bool valid = (yy >= 0) && (yy < 64) && (xx >= 0) && (xx < 64);
        const float* src = xn + yy * 64 + xx;
        #pragma unroll 4
        for (int i = 0; i < 64; i++) {
            const int c = cg + (i << 2);
            vsm[(c << 6) + p] = valid ? src[(size_t)c << 12] : 0.f;
        }
        __syncthreads();
        const float* wb = g_woT + ((tap << 8) << 5);
        #pragma unroll 2
        for (int c = 0; c < 256; c++) {
            float w = wb[(c << 5) + o];
            ull wd = pk2(w, w);
            const ulonglong2* vp = (const ulonglong2*)(vsm + (c << 6) + p0);
            ulonglong2 va = vp[0], vb = vp[1];
            ffma2(acc[0], wd, va.x);
            ffma2(acc[1], wd, va.y);
            ffma2(acc[2], wd, vb.x);
            ffma2(acc[3], wd, vb.y);
        }
        __syncthreads();
    }

    if (o < 27) {
        float f0,f1,f2,f3,f4,f5,f6,f7;
        upk2(acc[0], f0, f1); upk2(acc[1], f2, f3);
        upk2(acc[2], f4, f5); upk2(acc[3], f6, f7);
        float* op = g_om + (((size_t)(n * 27 + o) * 64 + y) << 6) + p0;
        *(float4*)op       = make_float4(f0, f1, f2, f3);
        *(float4*)(op + 4) = make_float4(f4, f5, f6, f7);
    }
}

// ---------------- DCNv2: gather + 9-tap GEMM, 1-row tiles -------------------
// Thread map: og = t>>3 (o-block of 8), pg = t&7 (8-pixel block of 64-px row).
// Packed dim = o-pair: acc[iop][jp] = (out[o0+2iop][p0+jp], out[o0+2iop+1][p0+jp]).
// Weights: 2 non-dup LDG.128/thread/c (pairs free in registers); values
// duplicated via movs from 2 LDS.128.
__global__ void __launch_bounds__(256, 2) k_dcn(const float* __restrict__ x,
                                                const float* __restrict__ bdcn) {
    extern __shared__ float vsm[];             // [256 c][64 p]
    const int t = threadIdx.x, y = blockIdx.x, n = blockIdx.y;
    const int og = t >> 3;
    const int o0 = og << 3;
    const int pg = t & 7;
    const int p0 = pg << 3;
    const int p  = t & 63;
    const int cg = t >> 6;

    ull acc[32];
    #pragma unroll
    for (int iop = 0; iop < 4; iop++) {
        ull bb = pk2(bdcn[o0 + 2 * iop], bdcn[o0 + 2 * iop + 1]);
        #pragma unroll
        for (int jp = 0; jp < 8; jp++) acc[iop * 8 + jp] = bb;
    }

    const float* xn = x + ((size_t)n << 20);

    for (int tap = 0; tap < 9; tap++) {
        const int ki = tap / 3, kj = tap - 3 * ki;
        const float offy = g_om[(((n * 27 + 2 * tap)     * 64 + y) << 6) + p];
        const float offx = g_om[(((n * 27 + 2 * tap + 1) * 64 + y) << 6) + p];
        const float mm   = g_om[(((n * 27 + 18 + tap)    * 64 + y) << 6) + p];
        const float mask = 1.f / (1.f + __expf(-mm));
        const float ys = (float)(y + ki - 1) + offy;
        const float xs = (float)(p + kj - 1) + offx;
        const float fy0 = floorf(ys), fx0 = floorf(xs);
        const float dy = ys - fy0, dx = xs - fx0;
        const int iy0 = (int)fy0, ix0 = (int)fx0;
        const int iy1 = iy0 + 1, ix1 = ix0 + 1;
        const bool vy0 = (iy0 >= 0) && (iy0 < 64), vy1 = (iy1 >= 0) && (iy1 < 64);
        const bool vx0 = (ix0 >= 0) && (ix0 < 64), vx1 = (ix1 >= 0) && (ix1 < 64);
        const float w00 = (vy0 && vx0) ? (1.f - dy) * (1.f - dx) * mask : 0.f;
        const float w01 = (vy0 && vx1) ? (1.f - dy) * dx * mask : 0.f;
        const float w10 = (vy1 && vx0) ? dy * (1.f - dx) * mask : 0.f;
        const float w11 = (vy1 && vx1) ? dy * dx * mask : 0.f;
        const int cy0 = min(max(iy0, 0), 63), cy1 = min(max(iy1, 0), 63);
        const int cx0 = min(max(ix0, 0), 63), cx1 = min(max(ix1, 0), 63);
        const int a00 = cy0 * 64 + cx0, a01 = cy0 * 64 + cx1;
        const int a10 = cy1 * 64 + cx0, a11 = cy1 * 64 + cx1;

        #pragma unroll 4
        for (int i = 0; i < 64; i++) {
            const int c = cg + (i << 2);
            const float* xc = xn + ((size_t)c << 12);
            vsm[(c << 6) + p] = w00 * xc[a00] + w01 * xc[a01]
                              + w10 * xc[a10] + w11 * xc[a11];
        }
        __syncthreads();

        const float* wt = g_wdT + (((size_t)tap << 8) << 8) + o0;
        #pragma unroll 1
        for (int c = 0; c < 256; c++) {
            const float4* wp = (const float4*)(wt + (c << 8));
            float4 wA = wp[0], wB = wp[1];
            ull wv[4] = { pk2(wA.x, wA.y), pk2(wA.z, wA.w),
                          pk2(wB.x, wB.y), pk2(wB.z, wB.w) };
            const float4* vp = (const float4*)(vsm + (c << 6) + p0);
            float4 vA = vp[0], vB = vp[1];
            ull vd[8] = { pk2(vA.x, vA.x), pk2(vA.y, vA.y),
                          pk2(vA.z, vA.z), pk2(vA.w, vA.w),
                          pk2(vB.x, vB.x), pk2(vB.y, vB.y),
                          pk2(vB.z, vB.z), pk2(vB.w, vB.w) };
            #pragma unroll
            for (int iop = 0; iop < 4; iop++)
                #pragma unroll
                for (int jp = 0; jp < 8; jp++)
                    ffma2(acc[iop * 8 + jp], wv[iop], vd[jp]);
        }
        __syncthreads();
    }

    float* ob = g_out1 + ((size_t)n << 20) + (y << 6) + p0;
    #pragma unroll
    for (int iop = 0; iop < 4; iop++) {
        float lo[8], hi[8];
        #pragma unroll
        for (int jp = 0; jp < 8; jp++) upk2(acc[iop * 8 + jp], lo[jp], hi[jp]);
        float* r0 = ob + ((size_t)(o0 + 2 * iop) << 12);
        float* r1 = ob + ((size_t)(o0 + 2 * iop + 1) << 12);
        *(float4*)r0       = make_float4(lo[0], lo[1], lo[2], lo[3]);
        *(float4*)(r0 + 4) = make_float4(lo[4], lo[5], lo[6], lo[7]);
        *(float4*)r1       = make_float4(hi[0], hi[1], hi[2], hi[3]);
        *(float4*)(r1 + 4) = make_float4(hi[4], hi[5], hi[6], hi[7]);
    }
}

// ---------------- per-channel reductions ------------------------------------
__global__ void k_red1() {
    int c = blockIdx.x, nb = blockIdx.y, t = threadIdx.x;
    const float4* p = (const float4*)(g_out1 + ((((size_t)nb << 8) + c) << 12));
    float s = 0.f, ss = 0.f;
    #pragma unroll
    for (int i = 0; i < 4; i++) {
        float4 v = p[t + (i << 8)];
        s  += v.x + v.y + v.z + v.w;
        ss += v.x * v.x + v.y * v.y + v.z * v.z + v.w * v.w;
    }
    for (int off = 16; off; off >>= 1) {
        s  += __shfl_down_sync(0xffffffffu, s, off);
        ss += __shfl_down_sync(0xffffffffu, ss, off);
    }
    __shared__ float as[8], bs[8];
    if ((t & 31) == 0) { as[t >> 5] = s; bs[t >> 5] = ss; }
    __syncthreads();
    if (t == 0) {
        float S = 0.f, SS = 0.f;
        for (int i = 0; i < 8; i++) { S += as[i]; SS += bs[i]; }
        atomicAdd(&g_red[c], (double)S);
        atomicAdd(&g_red[256 + c], (double)SS);
    }
}

__global__ void k_red2() {
    int c = blockIdx.x, q = blockIdx.y, t = threadIdx.x;
    const float4* p = (const float4*)(g_raw + ((((size_t)q << 8) + c) << 12));
    float s = 0.f, ss = 0.f;
    #pragma unroll
    for (int i = 0; i < 4; i++) {
        float4 v = p[t + (i << 8)];
        s  += v.x + v.y + v.z + v.w;
        ss += v.x * v.x + v.y * v.y + v.z * v.z + v.w * v.w;
    }
    for (int off = 16; off; off >>= 1) {
        s  += __shfl_down_sync(0xffffffffu, s, off);
        ss += __shfl_down_sync(0xffffffffu, ss, off);
    }
    __shared__ float as[8], bs[8];
    if ((t & 31) == 0) { as[t >> 5] = s; bs[t >> 5] = ss; }
    __syncthreads();
    if (t == 0) {
        float S = 0.f, SS = 0.f;
        for (int i = 0; i < 8; i++) { S += as[i]; SS += bs[i]; }
        atomicAdd(&g_red[512 + c], (double)S);
        atomicAdd(&g_red[768 + c], (double)SS);
    }
}

__global__ void k_stats1(const float* __restrict__ g, const float* __restrict__ b) {
    int t = threadIdx.x;
    double sum = g_red[t], sq = g_red[256 + t];
    double m = sum / 32768.0;
    float var = (float)(sq / 32768.0 - m * m);
    var = fmaxf(var, 0.f);
    float s = g[t] * rsqrtf(var + EPS);
    g_s1[t] = s;
    g_t1[t] = b[t] - (float)m * s;
}

__global__ void k_stats2(const float* __restrict__ g, const float* __restrict__ b) {
    int t = threadIdx.x;
    double sum = g_red[512 + t], sq = g_red[768 + t];
    double m = sum / 131072.0;
    float var = (float)(sq / 131072.0 - m * m);
    var = fmaxf(var, 0.f);
    float s = g[t] * rsqrtf(var + EPS);
    g_s2[t] = s;
    g_t2[t] = b[t] - (float)m * s;
}

// ---------------- conv transpose (per output parity, 4 taps), 1-row tiles ---
__global__ void __launch_bounds__(256, 2) k_convt() {
    extern __shared__ float sm[];
    float* vsm = sm;                 // [256][64]
    float* ssm = sm + 16384;         // s1
    float* tsm = sm + 16640;         // t1
    const int t = threadIdx.x, ty0 = blockIdx.x, n = blockIdx.y, par = blockIdx.z;
    const int py = par >> 1, px = par & 1;
    ssm[t] = g_s1[t];
    tsm[t] = g_t1[t];
    __syncthreads();

    const int og = t >> 3;
    const int o0 = og << 3;
    const int pg = t & 7;
    const int p0 = pg << 3;
    const int p  = t & 63;
    const int cg = t >> 6;

    ull acc[32];
    #pragma unroll
    for (int i = 0; i < 32; i++) acc[i] = 0ull;

    const float* srcn = g_out1 + ((size_t)n << 20);

    for (int tp = 0; tp < 4; tp++) {
        const int t_y = tp >> 1, t_x = tp & 1;
        const int yy = ty0 + t_y - 1 + py;
        const int xx = p + t_x - 1 + px;
        const bool valid = (yy >= 0) && (yy < 64) && (xx >= 0) && (xx < 64);
        const float* src = srcn + yy * 64 + xx;
        #pragma unroll 4
        for (int i = 0; i < 64; i++) {
            const int c = cg + (i << 2);
            float v = 0.f;
            if (valid) {
                float r = src[(size_t)c << 12];
                v = fmaxf(ssm[c] * r + tsm[c], 0.f);
            }
            vsm[(c << 6) + p] = v;
        }
        __syncthreads();

        const int q = par * 4 + tp;
        const float* wt = g_wctT + (((size_t)q << 8) << 8) + o0;
        #pragma unroll 1
        for (int c = 0; c < 256; c++) {
            const float4* wp = (const float4*)(wt + (c << 8));
            float4 wA = wp[0], wB = wp[1];
            ull wv[4] = { pk2(wA.x, wA.y), pk2(wA.z, wA.w),
                          pk2(wB.x, wB.y), pk2(wB.z, wB.w) };
            const float4* vp = (const float4*)(vsm + (c << 6) + p0);
            float4 vA = vp[0], vB = vp[1];
            ull vd[8] = { pk2(vA.x, vA.x), pk2(vA.y, vA.y),
                          pk2(vA.z, vA.z), pk2(vA.w, vA.w),
                          pk2(vB.x, vB.x), pk2(vB.y, vB.y),
                          pk2(vB.z, vB.z), pk2(vB.w, vB.w) };
            #pragma unroll
            for (int iop = 0; iop < 4; iop++)
                #pragma unroll
                for (int jp = 0; jp < 8; jp++)
                    ffma2(acc[iop * 8 + jp], wv[iop], vd[jp]);
        }
        __syncthreads();
    }

    float* ob = g_raw + (((size_t)par * 8 + n) << 20) + (ty0 << 6) + p0;
    #pragma unroll
    for (int iop = 0; iop < 4; iop++) {
        float lo[8], hi[8];
        #pragma unroll
        for (int jp = 0; jp < 8; jp++) upk2(acc[iop * 8 + jp], lo[jp], hi[jp]);
        float* r0 = ob + ((size_t)(o0 + 2 * iop) << 12);
        float* r1 = ob + ((size_t)(o0 + 2 * iop + 1) << 12);
        *(float4*)r0       = make_float4(lo[0], lo[1], lo[2], lo[3]);
        *(float4*)(r0 + 4) = make_float4(lo[4], lo[5], lo[6], lo[7]);
        *(float4*)r1       = make_float4(hi[0], hi[1], hi[2], hi[3]);
        *(float4*)(r1 + 4) = make_float4(hi[4], hi[5], hi[6], hi[7]);
    }
}

// ---------------- finalize: BN2 + ReLU, de-interleave parities --------------
__global__ void k_final(float* __restrict__ out) {
    int idx = blockIdx.x * 256 + threadIdx.x;
    int tx = idx & 63;
    int oy = (idx >> 6) & 127;
    int o  = (idx >> 13) & 255;
    int n  = idx >> 21;
    int py = oy & 1, ty = oy >> 1;
    size_t b0 = ((((size_t)(2 * py + 0) * 8 + n) * 256 + o) << 12) + (ty << 6) + tx;
    size_t b1 = ((((size_t)(2 * py + 1) * 8 + n) * 256 + o) << 12) + (ty << 6) + tx;
    float r0 = g_raw[b0], r1 = g_raw[b1];
    float s = g_s2[o], tt = g_t2[o];
    float2 w2;
    w2.x = fmaxf(s * r0 + tt, 0.f);
    w2.y = fmaxf(s * r1 + tt, 0.f);
    *(float2*)(out + ((((size_t)n * 256 + o) * 128 + oy) << 7) + 2 * tx) = w2;
}

// ---------------- launch ----------------------------------------------------
extern "C" void kernel_launch(void* const* d_in, const int* in_sizes, int n_in,
                              void* d_out, int out_size) {
    const float* x      = (const float*)d_in[0];
    const float* w_off  = (const float*)d_in[1];
    const float* b_off  = (const float*)d_in[2];
    const float* w_dcn  = (const float*)d_in[3];
    const float* b_dcn  = (const float*)d_in[4];
    const float* gamma1 = (const float*)d_in[5];
    const float* beta1  = (const float*)d_in[6];
    const float* w_ct   = (const float*)d_in[7];
    const float* gamma2 = (const float*)d_in[8];
    const float* beta2  = (const float*)d_in[9];
    float* out = (float*)d_out;

    cudaFuncSetAttribute(k_off,   cudaFuncAttributeMaxDynamicSharedMemorySize, 65536);
    cudaFuncSetAttribute(k_dcn,   cudaFuncAttributeMaxDynamicSharedMemorySize, 65536);
    cudaFuncSetAttribute(k_convt, cudaFuncAttributeMaxDynamicSharedMemorySize, 67584);

    prep_wd<<<(9 * 256 * 256 + 255) / 256, 256>>>(w_dcn);
    prep_wo<<<(9 * 256 * 32 + 255) / 256, 256>>>(w_off);
    prep_wct<<<(16 * 65536 + 255) / 256, 256>>>(w_ct);
    k_zero<<<1, 256>>>();

    k_off<<<dim3(64, 8), 256, 65536>>>(x, b_off);
    k_dcn<<<dim3(64, 8), 256, 65536>>>(x, b_dcn);

    k_red1<<<dim3(256, 8), 256>>>();
    k_stats1<<<1, 256>>>(gamma1, beta1);

    k_convt<<<dim3(64, 8, 4), 256, 67584>>>();

    k_red2<<<dim3(256, 32), 256>>>();
    k_stats2<<<1, 256>>>(gamma2, beta2);

    k_final<<<65536, 256>>>(out);
}

// round 7
// speedup vs baseline: 7.2704x; 2.6141x over previous
#include <cuda_runtime.h>
#include <cstdint>
#include <math.h>

typedef unsigned long long ull;

#define EPS 1e-5f

// ---------------- scratch (device globals; no allocations allowed) ----------
__device__ float  g_om[8 * 27 * 64 * 64];          // offset-conv output
__device__ float  g_out1[8 * 256 * 64 * 64];       // DCN output (pre-BN)
__device__ float  g_raw[4 * 8 * 256 * 64 * 64];    // convT output per parity (pre-BN)
__device__ float  g_wdT[9 * 256 * 256];            // DCN weights [tap][c][o], tf32 bits
__device__ float  g_wctT[16 * 256 * 256];          // convT weights [par*4+tp][c][o], tf32 bits
__device__ float  g_woT[9 * 256 * 32];             // offset-conv weights [tap][c][o(pad32)]
__device__ double g_red[1024];                     // sums/sumsqs for the two BNs
__device__ float  g_s1[256], g_t1[256], g_s2[256], g_t2[256];

// ---------------- packed f32x2 helpers (k_off only) --------------------------
__device__ __forceinline__ ull pk2(float a, float b) {
    ull r; asm("mov.b64 %0, {%1,%2};" : "=l"(r) : "f"(a), "f"(b)); return r;
}
__device__ __forceinline__ void upk2(ull v, float& a, float& b) {
    asm("mov.b64 {%0,%1}, %2;" : "=f"(a), "=f"(b) : "l"(v));
}
__device__ __forceinline__ void ffma2(ull& d, ull a, ull b) {
    asm("fma.rn.f32x2 %0, %1, %2, %0;" : "+l"(d) : "l"(a), "l"(b));
}

// ---------------- tf32 helpers -----------------------------------------------
__device__ __forceinline__ uint32_t to_tf32(float f) {
    uint32_t u; asm("cvt.rna.tf32.f32 %0, %1;" : "=r"(u) : "f"(f)); return u;
}

#define MMA_TF32(dd, aa, b0, b1) \
    asm volatile("mma.sync.aligned.m16n8k8.row.col.f32.tf32.tf32.f32 " \
        "{%0,%1,%2,%3}, {%4,%5,%6,%7}, {%8,%9}, {%0,%1,%2,%3};" \
        : "+f"((dd)[0]), "+f"((dd)[1]), "+f"((dd)[2]), "+f"((dd)[3]) \
        : "r"((aa)[0]), "r"((aa)[1]), "r"((aa)[2]), "r"((aa)[3]), \
          "r"(b0), "r"(b1))

// SMEM float-index layout for both mma kernels:
//   [0:256)   aux0 (bias / s1)     [256:512) aux1 (t1)
//   [512:2816)  A tile [32 k][72]  (64 px used, pad to 72)
//   [2816:11264) B tile [32 k][264] (256 o used, pad to 264)
#define SMF_A   512
#define SMF_B   2816
#define SM_SZ   (11264 * 4)

// ---------------- weight prep -----------------------------------------------
__global__ void prep_wd(const float* __restrict__ w) {  // w_dcn [o][c][3][3]
    int idx = blockIdx.x * blockDim.x + threadIdx.x;
    if (idx >= 9 * 65536) return;
    int tap = idx >> 16, c = (idx >> 8) & 255, o = idx & 255;
    g_wdT[idx] = __uint_as_float(to_tf32(w[((o << 8) + c) * 9 + tap]));
}

__global__ void prep_wct(const float* __restrict__ w) {  // w_ct [i][o][4][4]
    int idx = blockIdx.x * blockDim.x + threadIdx.x;
    if (idx >= 16 * 65536) return;
    int q = idx >> 16, c = (idx >> 8) & 255, o = idx & 255;
    int par = q >> 2, tp = q & 3;
    int py = par >> 1, px = par & 1, ty = tp >> 1, tx = tp & 1;
    int a = py ? (ty ? 0 : 2) : (ty ? 1 : 3);
    int b = px ? (tx ? 0 : 2) : (tx ? 1 : 3);
    g_wctT[idx] = __uint_as_float(to_tf32(w[(((c << 8) + o) << 4) + (a << 2) + b]));
}

__global__ void prep_wo(const float* __restrict__ w) {  // w_off [27][c][3][3]
    int idx = blockIdx.x * blockDim.x + threadIdx.x;
    if (idx >= 9 * 256 * 32) return;
    int tap = idx >> 13, c = (idx >> 5) & 255, o = idx & 31;
    g_woT[idx] = (o < 27) ? w[((o << 8) + c) * 9 + tap] : 0.f;
}

__global__ void k_zero() {
    int t = threadIdx.x;
    g_red[t] = 0.0; g_red[256 + t] = 0.0; g_red[512 + t] = 0.0; g_red[768 + t] = 0.0;
}

// ---------------- offset conv: 256->27(pad 32), 3x3 SAME (fp32, exact) ------
__global__ void __launch_bounds__(256, 2) k_off(const float* __restrict__ x,
                                                const float* __restrict__ boff) {
    extern __shared__ float vsm[];             // [256 c][64 p]
    const int t = threadIdx.x, y = blockIdx.x, n = blockIdx.y;
    const int o  = t & 31;
    const int p0 = (t >> 5) * 8;
    const int p  = t & 63;
    const int cg = t >> 6;

    ull acc[4];
    float bo = (o < 27) ? boff[o] : 0.f;
    ull bb = pk2(bo, bo);
    acc[0] = bb; acc[1] = bb; acc[2] = bb; acc[3] = bb;

    const float* xn = x + ((size_t)n << 20);

    for (int tap = 0; tap < 9; tap++) {
        const int ki = tap / 3, kj = tap - 3 * ki;
        const int yy = y + ki - 1;
        const int xx = p + kj - 1;
        const bool valid = (yy >= 0) && (yy < 64) && (xx >= 0) && (xx < 64);
        const float* src = xn + yy * 64 + xx;
        #pragma unroll 4
        for (int i = 0; i < 64; i++) {
            const int c = cg + (i << 2);
            vsm[(c << 6) + p] = valid ? src[(size_t)c << 12] : 0.f;
        }
        __syncthreads();
        const float* wb = g_woT + ((tap << 8) << 5);
        #pragma unroll 2
        for (int c = 0; c < 256; c++) {
            float w = wb[(c << 5) + o];
            ull wd = pk2(w, w);
            const ulonglong2* vp = (const ulonglong2*)(vsm + (c << 6) + p0);
            ulonglong2 va = vp[0], vb = vp[1];
            ffma2(acc[0], wd, va.x);
            ffma2(acc[1], wd, va.y);
            ffma2(acc[2], wd, vb.x);
            ffma2(acc[3], wd, vb.y);
        }
        __syncthreads();
    }

    if (o < 27) {
        float f0,f1,f2,f3,f4,f5,f6,f7;
        upk2(acc[0], f0, f1); upk2(acc[1], f2, f3);
        upk2(acc[2], f4, f5); upk2(acc[3], f6, f7);
        float* op = g_om + (((size_t)(n * 27 + o) * 64 + y) << 6) + p0;
        *(float4*)op       = make_float4(f0, f1, f2, f3);
        *(float4*)(op + 4) = make_float4(f4, f5, f6, f7);
    }
}

// ---------------- DCNv2 via tf32 mma.sync: M=64px, N=256o, K=9x256 ----------
__global__ void __launch_bounds__(256, 2) k_dcn_mma(const float* __restrict__ x,
                                                    const float* __restrict__ bdcn) {
    extern __shared__ __align__(16) float smf[];
    const int t = threadIdx.x, y = blockIdx.x, n = blockIdx.y;
    const int wid = t >> 5, lane = t & 31;
    const int g = lane >> 2, tid = lane & 3;
    const int p = t & 63, cq = t >> 6;

    smf[t] = (t < 256) ? bdcn[t] : 0.f;       // bias in [0:256)

    float d[4][4][4];
    #pragma unroll
    for (int i = 0; i < 4; i++)
        #pragma unroll
        for (int j = 0; j < 4; j++)
            #pragma unroll
            for (int k = 0; k < 4; k++) d[i][j][k] = 0.f;

    const float* xn = x + ((size_t)n << 20);
    float wr0 = 0.f, wr1 = 0.f, wc0 = 0.f, wc1 = 0.f;
    int abase = 0;

    for (int it = 0; it < 72; it++) {
        const int tap = it >> 3, kc = it & 7;
        if (kc == 0) {
            const int ki = tap / 3, kj = tap - 3 * ki;
            const float offy = g_om[(((n * 27 + 2 * tap)     * 64 + y) << 6) + p];
            const float offx = g_om[(((n * 27 + 2 * tap + 1) * 64 + y) << 6) + p];
            const float mm   = g_om[(((n * 27 + 18 + tap)    * 64 + y) << 6) + p];
            const float mask = 1.f / (1.f + __expf(-mm));
            const float ys = (float)(y + ki - 1) + offy;
            const float xs = (float)(p + kj - 1) + offx;
            const float fy0 = floorf(ys), fx0 = floorf(xs);
            const float dy = ys - fy0, dx = xs - fx0;
            const int iy0 = (int)fy0, ix0 = (int)fx0;
            wr0 = (iy0 >= 0 && iy0 <= 62) ? (1.f - dy) : ((iy0 == -1) ? dy : 0.f);
            wr1 = (iy0 >= 0 && iy0 <= 62) ? dy : ((iy0 == 63) ? (1.f - dy) : 0.f);
            wc0 = (ix0 >= 0 && ix0 <= 62) ? (1.f - dx) : ((ix0 == -1) ? dx : 0.f);
            wc1 = (ix0 >= 0 && ix0 <= 62) ? dx : ((ix0 == 63) ? (1.f - dx) : 0.f);
            wr0 *= mask; wr1 *= mask;
            const int rb = min(max(iy0, 0), 62), cb = min(max(ix0, 0), 62);
            abase = rb * 64 + cb;
        }
        __syncthreads();
        // stage B: 32x256 tf32 weights -> [32][264]
        {
            const float4* srcB = (const float4*)(g_wdT + (((size_t)(tap << 8) + (kc << 5)) << 8));
            #pragma unroll
            for (int i = 0; i < 8; i++) {
                int idx = t + (i << 8);
                float4 f4 = srcB[idx];
                int cl = idx >> 6, o4 = (idx & 63) << 2;
                *(float4*)(smf + SMF_B + cl * 264 + o4) = f4;
            }
        }
        // stage A: bilinear gather -> [32][72], tf32
        {
            #pragma unroll
            for (int j = 0; j < 8; j++) {
                const int cl = (cq << 3) + j;
                const float* xc = xn + ((size_t)((kc << 5) + cl) << 12);
                float v = wr0 * (wc0 * xc[abase]      + wc1 * xc[abase + 1])
                        + wr1 * (wc0 * xc[abase + 64] + wc1 * xc[abase + 65]);
                smf[SMF_A + cl * 72 + p] = __uint_as_float(to_tf32(v));
            }
        }
        __syncthreads();
        // mma phase
        const uint32_t* Au = (const uint32_t*)(smf + SMF_A);
        const uint32_t* Bu = (const uint32_t*)(smf + SMF_B);
        #pragma unroll
        for (int ks = 0; ks < 4; ks++) {
            const int k0 = (ks << 3) + tid;
            uint32_t a[4][4];
            #pragma unroll
            for (int mt = 0; mt < 4; mt++) {
                const int r0 = (mt << 4) + g;
                a[mt][0] = Au[k0 * 72 + r0];
                a[mt][1] = Au[k0 * 72 + r0 + 8];
                a[mt][2] = Au[(k0 + 4) * 72 + r0];
                a[mt][3] = Au[(k0 + 4) * 72 + r0 + 8];
            }
            #pragma unroll
            for (int nt = 0; nt < 4; nt++) {
                const int nb = (wid << 5) + (nt << 3) + g;
                uint32_t b0 = Bu[k0 * 264 + nb];
                uint32_t b1 = Bu[(k0 + 4) * 264 + nb];
                #pragma unroll
                for (int mt = 0; mt < 4; mt++)
                    MMA_TF32(d[mt][nt], a[mt], b0, b1);
            }
        }
    }

    // epilogue: +bias, store to g_out1[n][o][y][x]
    float* ob = g_out1 + ((size_t)n << 20) + (y << 6);
    #pragma unroll
    for (int mt = 0; mt < 4; mt++) {
        const int x0 = (mt << 4) + g;
        #pragma unroll
        for (int nt = 0; nt < 4; nt++) {
            const int o0 = (wid << 5) + (nt << 3) + (tid << 1);
            const float b0v = smf[o0], b1v = smf[o0 + 1];
            ob[((size_t)o0 << 12) + x0]           = d[mt][nt][0] + b0v;
            ob[((size_t)(o0 + 1) << 12) + x0]     = d[mt][nt][1] + b1v;
            ob[((size_t)o0 << 12) + x0 + 8]       = d[mt][nt][2] + b0v;
            ob[((size_t)(o0 + 1) << 12) + x0 + 8] = d[mt][nt][3] + b1v;
        }
    }
}

// ---------------- convT via tf32 mma.sync: per parity, K=4x256 --------------
__global__ void __launch_bounds__(256, 2) k_convt_mma() {
    extern __shared__ __align__(16) float smf[];
    const int t = threadIdx.x, y = blockIdx.x, n = blockIdx.y, par = blockIdx.z;
    const int py = par >> 1, pxs = par & 1;
    const int wid = t >> 5, lane = t & 31;
    const int g = lane >> 2, tid = lane & 3;
    const int p = t & 63, cq = t >> 6;

    smf[t] = g_s1[t];
    smf[256 + t] = g_t1[t];

    float d[4][4][4];
    #pragma unroll
    for (int i = 0; i < 4; i++)
        #pragma unroll
        for (int j = 0; j < 4; j++)
            #pragma unroll
            for (int k = 0; k < 4; k++) d[i][j][k] = 0.f;

    const float* srcn = g_out1 + ((size_t)n << 20);
    int soff = 0; bool valid = false;

    for (int it = 0; it < 32; it++) {
        const int tp = it >> 3, kc = it & 7;
        if (kc == 0) {
            const int t_y = tp >> 1, t_x = tp & 1;
            const int yy = y + t_y - 1 + py;
            const int xx = p + t_x - 1 + pxs;
            valid = (yy >= 0) && (yy < 64) && (xx >= 0) && (xx < 64);
            soff = valid ? (yy * 64 + xx) : 0;
        }
        __syncthreads();
        {
            const int q = par * 4 + tp;
            const float4* srcB = (const float4*)(g_wctT + (((size_t)(q << 8) + (kc << 5)) << 8));
            #pragma unroll
            for (int i = 0; i < 8; i++) {
                int idx = t + (i << 8);
                float4 f4 = srcB[idx];
                int cl = idx >> 6, o4 = (idx & 63) << 2;
                *(float4*)(smf + SMF_B + cl * 264 + o4) = f4;
            }
        }
        {
            #pragma unroll
            for (int j = 0; j < 8; j++) {
                const int cl = (cq << 3) + j;
                const int c = (kc << 5) + cl;
                float v = 0.f;
                if (valid) {
                    float r = srcn[((size_t)c << 12) + soff];
                    v = fmaxf(smf[c] * r + smf[256 + c], 0.f);
                }
                smf[SMF_A + cl * 72 + p] = __uint_as_float(to_tf32(v));
            }
        }
        __syncthreads();
        const uint32_t* Au = (const uint32_t*)(smf + SMF_A);
        const uint32_t* Bu = (const uint32_t*)(smf + SMF_B);
        #pragma unroll
        for (int ks = 0; ks < 4; ks++) {
            const int k0 = (ks << 3) + tid;
            uint32_t a[4][4];
            #pragma unroll
            for (int mt = 0; mt < 4; mt++) {
                const int r0 = (mt << 4) + g;
                a[mt][0] = Au[k0 * 72 + r0];
                a[mt][1] = Au[k0 * 72 + r0 + 8];
                a[mt][2] = Au[(k0 + 4) * 72 + r0];
                a[mt][3] = Au[(k0 + 4) * 72 + r0 + 8];
            }
            #pragma unroll
            for (int nt = 0; nt < 4; nt++) {
                const int nb = (wid << 5) + (nt << 3) + g;
                uint32_t b0 = Bu[k0 * 264 + nb];
                uint32_t b1 = Bu[(k0 + 4) * 264 + nb];
                #pragma unroll
                for (int mt = 0; mt < 4; mt++)
                    MMA_TF32(d[mt][nt], a[mt], b0, b1);
            }
        }
    }

    float* ob = g_raw + (((size_t)par * 8 + n) << 20) + (y << 6);
    #pragma unroll
    for (int mt = 0; mt < 4; mt++) {
        const int x0 = (mt << 4) + g;
        #pragma unroll
        for (int nt = 0; nt < 4; nt++) {
            const int o0 = (wid << 5) + (nt << 3) + (tid << 1);
            ob[((size_t)o0 << 12) + x0]           = d[mt][nt][0];
            ob[((size_t)(o0 + 1) << 12) + x0]     = d[mt][nt][1];
            ob[((size_t)o0 << 12) + x0 + 8]       = d[mt][nt][2];
            ob[((size_t)(o0 + 1) << 12) + x0 + 8] = d[mt][nt][3];
        }
    }
}

// ---------------- per-channel reductions ------------------------------------
__global__ void k_red1() {
    int c = blockIdx.x, nb = blockIdx.y, t = threadIdx.x;
    const float4* p = (const float4*)(g_out1 + ((((size_t)nb << 8) + c) << 12));
    float s = 0.f, ss = 0.f;
    #pragma unroll
    for (int i = 0; i < 4; i++) {
        float4 v = p[t + (i << 8)];
        s  += v.x + v.y + v.z + v.w;
        ss += v.x * v.x + v.y * v.y + v.z * v.z + v.w * v.w;
    }
    for (int off = 16; off; off >>= 1) {
        s  += __shfl_down_sync(0xffffffffu, s, off);
        ss += __shfl_down_sync(0xffffffffu, ss, off);
    }
    __shared__ float as[8], bs[8];
    if ((t & 31) == 0) { as[t >> 5] = s; bs[t >> 5] = ss; }
    __syncthreads();
    if (t == 0) {
        float S = 0.f, SS = 0.f;
        for (int i = 0; i < 8; i++) { S += as[i]; SS += bs[i]; }
        atomicAdd(&g_red[c], (double)S);
        atomicAdd(&g_red[256 + c], (double)SS);
    }
}

__global__ void k_red2() {
    int c = blockIdx.x, q = blockIdx.y, t = threadIdx.x;
    const float4* p = (const float4*)(g_raw + ((((size_t)q << 8) + c) << 12));
    float s = 0.f, ss = 0.f;
    #pragma unroll
    for (int i = 0; i < 4; i++) {
        float4 v = p[t + (i << 8)];
        s  += v.x + v.y + v.z + v.w;
        ss += v.x * v.x + v.y * v.y + v.z * v.z + v.w * v.w;
    }
    for (int off = 16; off; off >>= 1) {
        s  += __shfl_down_sync(0xffffffffu, s, off);
        ss += __shfl_down_sync(0xffffffffu, ss, off);
    }
    __shared__ float as[8], bs[8];
    if ((t & 31) == 0) { as[t >> 5] = s; bs[t >> 5] = ss; }
    __syncthreads();
    if (t == 0) {
        float S = 0.f, SS = 0.f;
        for (int i = 0; i < 8; i++) { S += as[i]; SS += bs[i]; }
        atomicAdd(&g_red[512 + c], (double)S);
        atomicAdd(&g_red[768 + c], (double)SS);
    }
}

__global__ void k_stats1(const float* __restrict__ g, const float* __restrict__ b) {
    int t = threadIdx.x;
    double sum = g_red[t], sq = g_red[256 + t];
    double m = sum / 32768.0;
    float var = (float)(sq / 32768.0 - m * m);
    var = fmaxf(var, 0.f);
    float s = g[t] * rsqrtf(var + EPS);
    g_s1[t] = s;
    g_t1[t] = b[t] - (float)m * s;
}

__global__ void k_stats2(const float* __restrict__ g, const float* __restrict__ b) {
    int t = threadIdx.x;
    double sum = g_red[512 + t], sq = g_red[768 + t];
    double m = sum / 131072.0;
    float var = (float)(sq / 131072.0 - m * m);
    var = fmaxf(var, 0.f);
    float s = g[t] * rsqrtf(var + EPS);
    g_s2[t] = s;
    g_t2[t] = b[t] - (float)m * s;
}

// ---------------- finalize: BN2 + ReLU, de-interleave parities --------------
__global__ void k_final(float* __restrict__ out) {
    int idx = blockIdx.x * 256 + threadIdx.x;
    int tx = idx & 63;
    int oy = (idx >> 6) & 127;
    int o  = (idx >> 13) & 255;
    int n  = idx >> 21;
    int py = oy & 1, ty = oy >> 1;
    size_t b0 = ((((size_t)(2 * py + 0) * 8 + n) * 256 + o) << 12) + (ty << 6) + tx;
    size_t b1 = ((((size_t)(2 * py + 1) * 8 + n) * 256 + o) << 12) + (ty << 6) + tx;
    float r0 = g_raw[b0], r1 = g_raw[b1];
    float s = g_s2[o], tt = g_t2[o];
    float2 w2;
    w2.x = fmaxf(s * r0 + tt, 0.f);
    w2.y = fmaxf(s * r1 + tt, 0.f);
    *(float2*)(out + ((((size_t)n * 256 + o) * 128 + oy) << 7) + 2 * tx) = w2;
}

// ---------------- launch ----------------------------------------------------
extern "C" void kernel_launch(void* const* d_in, const int* in_sizes, int n_in,
                              void* d_out, int out_size) {
    const float* x      = (const float*)d_in[0];
    const float* w_off  = (const float*)d_in[1];
    const float* b_off  = (const float*)d_in[2];
    const float* w_dcn  = (const float*)d_in[3];
    const float* b_dcn  = (const float*)d_in[4];
    const float* gamma1 = (const float*)d_in[5];
    const float* beta1  = (const float*)d_in[6];
    const float* w_ct   = (const float*)d_in[7];
    const float* gamma2 = (const float*)d_in[8];
    const float* beta2  = (const float*)d_in[9];
    float* out = (float*)d_out;

    cudaFuncSetAttribute(k_off,       cudaFuncAttributeMaxDynamicSharedMemorySize, 65536);
    cudaFuncSetAttribute(k_dcn_mma,   cudaFuncAttributeMaxDynamicSharedMemorySize, SM_SZ);
    cudaFuncSetAttribute(k_convt_mma, cudaFuncAttributeMaxDynamicSharedMemorySize, SM_SZ);

    prep_wd<<<(9 * 65536 + 255) / 256, 256>>>(w_dcn);
    prep_wct<<<(16 * 65536 + 255) / 256, 256>>>(w_ct);
    prep_wo<<<(9 * 256 * 32 + 255) / 256, 256>>>(w_off);
    k_zero<<<1, 256>>>();

    k_off<<<dim3(64, 8), 256, 65536>>>(x, b_off);
    k_dcn_mma<<<dim3(64, 8), 256, SM_SZ>>>(x, b_dcn);

    k_red1<<<dim3(256, 8), 256>>>();
    k_stats1<<<1, 256>>>(gamma1, beta1);

    k_convt_mma<<<dim3(64, 8, 4), 256, SM_SZ>>>();

    k_red2<<<dim3(256, 32), 256>>>();
    k_stats2<<<1, 256>>>(gamma2, beta2);

    k_final<<<65536, 256>>>(out);
}